// round 7
// baseline (speedup 1.0000x reference)
#include <cuda_runtime.h>
#include <cstdint>

// Problem constants
#define Bx 256
#define Tx 3000
#define Ix 40
#define Hx 64
#define Gx 256        // 4*H gates
#define RCH 8         // recurrent x_proj chunk steps (3000 % 8 == 0 -> 375 chunks)
#define XTK 50        // xproj tokens per block tile (3000 % 50 == 0)

// Scratch (allocation-free rule: __device__ globals)
__device__ float g_h[2][(size_t)Bx * Tx * Hx];    // per-direction hidden outputs
__device__ float g_xp[2][(size_t)Bx * Tx * Gx];   // input projections (+biases); dir1 time-reversed

// ---------- packed f32x2 helpers ----------
union F2U { float2 f; unsigned long long u; };

__device__ __forceinline__ void ffma2(unsigned long long& acc,
                                      unsigned long long a,
                                      unsigned long long b) {
    asm("fma.rn.f32x2 %0, %1, %2, %0;" : "+l"(acc) : "l"(a), "l"(b));
}
__device__ __forceinline__ unsigned long long fadd2(unsigned long long a, unsigned long long b) {
    unsigned long long r;
    asm("add.rn.f32x2 %0, %1, %2;" : "=l"(r) : "l"(a), "l"(b));
    return r;
}
__device__ __forceinline__ float fsigmoid(float x) {
    return __fdividef(1.0f, 1.0f + __expf(-x));
}
__device__ __forceinline__ float ftanh_fast(float x) {
    return 1.0f - __fdividef(2.0f, __expf(2.0f * x) + 1.0f);
}
__device__ __forceinline__ float hsum2(unsigned long long a, unsigned long long b) {
    F2U s; s.u = fadd2(a, b);
    return s.f.x + s.f.y;
}

// ---------- cp.async helpers ----------
__device__ __forceinline__ unsigned int smem_u32(const void* p) {
    return (unsigned int)__cvta_generic_to_shared(p);
}
__device__ __forceinline__ void cp_async16(unsigned int s, const void* g) {
    asm volatile("cp.async.cg.shared.global [%0], [%1], 16;" :: "r"(s), "l"(g));
}
#define CP_COMMIT() asm volatile("cp.async.commit_group;")
#define CP_WAIT1()  asm volatile("cp.async.wait_group 1;")

// ================= x-projection kernel =================
// ONE direction per block (low regs -> 4 blocks/SM). Thread g = gate g.
// 2-token unroll; dir1 output stored time-reversed.
__global__ __launch_bounds__(256, 4)
void xproj_kernel(const float* __restrict__ x,
                  const float* __restrict__ WihF, const float* __restrict__ bihF,
                  const float* __restrict__ bhhF,
                  const float* __restrict__ WihB, const float* __restrict__ bihB,
                  const float* __restrict__ bhhB)
{
    const int g = threadIdx.x;
    __shared__ __align__(16) float sx[XTK * Ix];   // 8 KB

    const int dir  = blockIdx.x & 1;
    const int rest = blockIdx.x >> 1;
    const int tiles = Tx / XTK;                    // 60
    const int batch = rest / tiles;
    const int trel  = (rest % tiles) * XTK;

    const float* Wih = dir ? WihB : WihF;
    unsigned long long w[20];
    {
        const float2* wr = (const float2*)(Wih + (size_t)g * Ix);
        #pragma unroll
        for (int j = 0; j < 20; j++) { F2U u; u.f = wr[j]; w[j] = u.u; }
    }
    const float bias = dir ? (bihB[g] + bhhB[g]) : (bihF[g] + bhhF[g]);

    {
        const float4* xs = (const float4*)(x + ((size_t)batch * Tx + trel) * Ix);
        float4* sd = (float4*)sx;
        #pragma unroll
        for (int i = 0; i < 2; i++) {
            int idx = threadIdx.x + i * 256;
            if (idx < XTK * Ix / 4) sd[idx] = xs[idx];
        }
    }
    __syncthreads();

    const int t0 = dir ? (Tx - 1 - trel) : trel;
    const ptrdiff_t pstep = dir ? -(ptrdiff_t)Gx : (ptrdiff_t)Gx;
    float* p = g_xp[dir] + ((size_t)batch * Tx + t0) * Gx + g;
    const ulonglong2* xr = (const ulonglong2*)sx;

    #pragma unroll 1
    for (int k = 0; k < XTK / 2; k++) {
        F2U a0, a1, b0, b1;
        a0.f = make_float2(bias, 0.0f); a1.f = make_float2(0.0f, 0.0f);
        b0 = a0; b1 = a1;
        #pragma unroll
        for (int j = 0; j < 10; j++) {
            const ulonglong2 ua = xr[j];        // token 2k
            const ulonglong2 ub = xr[10 + j];   // token 2k+1
            ffma2(a0.u, ua.x, w[2 * j]);  ffma2(a1.u, ua.y, w[2 * j + 1]);
            ffma2(b0.u, ub.x, w[2 * j]);  ffma2(b1.u, ub.y, w[2 * j + 1]);
        }
        xr += 20;
        p[0]          = hsum2(a0.u, a1.u);
        *(p + pstep)  = hsum2(b0.u, b1.u);
        p += 2 * pstep;
    }
}

// ================= recurrent LSTM kernel =================
// Transposed assignment: thread (seq s, idx u) computes ALL FOUR gates for
// h[u] of its sequence (4 W_hh rows = 128 regs). No gate exchange; double-
// buffered sh -> ONE __syncthreads per timestep.
// 256 blocks x 128 threads (2 seqs/block), 2 blocks/SM (overlapping domains).
__global__ __launch_bounds__(128, 2)
void lstm_kernel(const float* __restrict__ Whh_f, const float* __restrict__ Whh_b)
{
    const int dir   = blockIdx.x >> 7;          // 0..127 fwd, 128..255 bwd
    const int bbase = (blockIdx.x & 127) * 2;   // batches bbase, bbase+1

    const float* Whh = dir ? Whh_b : Whh_f;
    float* hout = g_h[dir];
    const float* xpd = g_xp[dir];

    const int tid = threadIdx.x;
    const int s   = tid >> 6;                   // local sequence 0/1
    const int u   = tid & 63;                   // h index

    __shared__ __align__(16) float sxp[2][2][RCH * Gx];  // [seq][buf] 32 KB
    __shared__ __align__(16) float sh[2][2][Hx];         // [parity][seq] 1 KB

    // four W_hh rows (gates i,f,g,o for index u) in registers
    unsigned long long wI[32], wF[32], wG[32], wO[32];
    {
        const float2* rI = (const float2*)(Whh + (size_t)(0 * 64 + u) * Hx);
        const float2* rF = (const float2*)(Whh + (size_t)(1 * 64 + u) * Hx);
        const float2* rG = (const float2*)(Whh + (size_t)(2 * 64 + u) * Hx);
        const float2* rO = (const float2*)(Whh + (size_t)(3 * 64 + u) * Hx);
        #pragma unroll
        for (int j = 0; j < 32; j++) { F2U a; a.f = rI[j]; wI[j] = a.u; }
        #pragma unroll
        for (int j = 0; j < 32; j++) { F2U a; a.f = rF[j]; wF[j] = a.u; }
        #pragma unroll
        for (int j = 0; j < 32; j++) { F2U a; a.f = rG[j]; wG[j] = a.u; }
        #pragma unroll
        for (int j = 0; j < 32; j++) { F2U a; a.f = rO[j]; wO[j] = a.u; }
    }

    sh[0][s][u] = 0.0f;
    float c = 0.0f;

    // cp.async slice: thread stages 128B of its own sequence's chunk
    const char* xsrc = (const char*)(xpd + (size_t)(bbase + s) * Tx * Gx) + u * 128;
    const unsigned int sdst0 = smem_u32(&sxp[s][0][0]) + u * 128;
    const unsigned int sdst1 = smem_u32(&sxp[s][1][0]) + u * 128;
    const int CHBYTES = RCH * Gx * 4;   // 8192

    // h output pointer for (bbase+s, u)
    float* hptr = hout + ((size_t)(bbase + s) * Tx + (dir ? (Tx - 1) : 0)) * Hx + u;
    const ptrdiff_t hstep = dir ? -Hx : Hx;

    // prefetch chunk 0 into buffer 0 (8 x 16B)
    #pragma unroll
    for (int i = 0; i < 8; i++) cp_async16(sdst0 + i * 16, xsrc + i * 16);
    CP_COMMIT();

    int par = 0;
    const int NCH = Tx / RCH;
    for (int ck = 0; ck < NCH; ck++) {
        // prefetch next chunk; wait for CURRENT; barrier
        if (ck + 1 < NCH) {
            const unsigned int sdst = ((ck + 1) & 1) ? sdst1 : sdst0;
            const char* gsrc = xsrc + (size_t)(ck + 1) * CHBYTES;
            #pragma unroll
            for (int i = 0; i < 8; i++) cp_async16(sdst + i * 16, gsrc + i * 16);
        }
        CP_COMMIT();
        CP_WAIT1();            // chunk ck landed; ck+1 in flight
        __syncthreads();       // copies + sh init / prior writes visible

        const float* xb = sxp[s][ck & 1];

        #pragma unroll 1
        for (int si = 0; si < RCH; si++) {
            // x-projection terms for the 4 gates (conflict-free LDS.32)
            const float xi = xb[si * Gx + u];
            const float xf = xb[si * Gx + 64 + u];
            const float xg = xb[si * Gx + 128 + u];
            const float xo = xb[si * Gx + 192 + u];

            F2U aI0, aI1, aF0, aF1, aG0, aG1, aO0, aO1;
            aI0.f = make_float2(xi, 0.0f); aI1.f = make_float2(0.0f, 0.0f);
            aF0.f = make_float2(xf, 0.0f); aF1.f = aI1.f;
            aG0.f = make_float2(xg, 0.0f); aG1.f = aI1.f;
            aO0.f = make_float2(xo, 0.0f); aO1.f = aI1.f;

            const ulonglong2* hv = (const ulonglong2*)sh[par][s];  // broadcast
            #pragma unroll
            for (int k = 0; k < 16; k++) {
                const ulonglong2 h4 = hv[k];           // 1 LDS.128 -> 8 FFMA2
                ffma2(aI0.u, h4.x, wI[2 * k]);  ffma2(aI1.u, h4.y, wI[2 * k + 1]);
                ffma2(aF0.u, h4.x, wF[2 * k]);  ffma2(aF1.u, h4.y, wF[2 * k + 1]);
                ffma2(aG0.u, h4.x, wG[2 * k]);  ffma2(aG1.u, h4.y, wG[2 * k + 1]);
                ffma2(aO0.u, h4.x, wO[2 * k]);  ffma2(aO1.u, h4.y, wO[2 * k + 1]);
            }
            const float vI = hsum2(aI0.u, aI1.u);
            const float vF = hsum2(aF0.u, aF1.u);
            const float vG = hsum2(aG0.u, aG1.u);
            const float vO = hsum2(aO0.u, aO1.u);

            c = fsigmoid(vF) * c + fsigmoid(vI) * ftanh_fast(vG);
            const float h = fsigmoid(vO) * ftanh_fast(c);

            sh[par ^ 1][s][u] = h;   // write OTHER buffer: no read/write conflict
            *hptr = h;
            hptr += hstep;
            par ^= 1;
            __syncthreads();         // single barrier per timestep
        }
    }
}

// ================= MLP head kernel =================
// 2 lanes per token (hf/hb halves), shfl-combine per output unit.
__global__ __launch_bounds__(256, 2)
void head_kernel(const float* __restrict__ W1, const float* __restrict__ b1,
                 const float* __restrict__ W2, const float* __restrict__ b2,
                 float* __restrict__ out)
{
    __shared__ __align__(16) float sW1[64 * 128];  // 32 KB
    __shared__ float sb1[64];
    __shared__ float sW2[64];

    const int tid = threadIdx.x;
    for (int i = tid; i < 64 * 128 / 4; i += 256)
        ((float4*)sW1)[i] = ((const float4*)W1)[i];
    if (tid < 64) { sb1[tid] = b1[tid]; sW2[tid] = W2[tid]; }
    __syncthreads();
    const float bias2 = b2[0];

    const size_t tok = (size_t)blockIdx.x * 128 + (tid >> 1);
    const int hsel = tid & 1;

    unsigned long long hreg[32];
    {
        const ulonglong2* hv = (const ulonglong2*)(g_h[hsel] + tok * Hx);
        #pragma unroll
        for (int j = 0; j < 16; j++) {
            ulonglong2 u = hv[j];
            hreg[2 * j] = u.x; hreg[2 * j + 1] = u.y;
        }
    }

    float acc = bias2;
    #pragma unroll 4
    for (int o = 0; o < 64; o++) {
        const unsigned long long* w =
            (const unsigned long long*)(sW1 + o * 128 + hsel * 64);
        F2U a0, a1, a2, a3;
        a0.f = make_float2(0.0f, 0.0f);
        a1 = a0; a2 = a0; a3 = a0;
        #pragma unroll
        for (int j = 0; j < 8; j++) {
            ffma2(a0.u, hreg[j],      w[j]);
            ffma2(a1.u, hreg[8 + j],  w[8 + j]);
            ffma2(a2.u, hreg[16 + j], w[16 + j]);
            ffma2(a3.u, hreg[24 + j], w[24 + j]);
        }
        F2U sx; sx.u = fadd2(fadd2(a0.u, a1.u), fadd2(a2.u, a3.u));
        float v = sx.f.x + sx.f.y;
        v += __shfl_xor_sync(0xffffffffu, v, 1);
        const float z = fmaxf(v + sb1[o], 0.0f);
        acc = fmaf(z, sW2[o], acc);
    }
    if (hsel == 0) out[tok] = fsigmoid(acc);
}

// ================= launch =================
extern "C" void kernel_launch(void* const* d_in, const int* in_sizes, int n_in,
                              void* d_out, int out_size)
{
    const float* x     = (const float*)d_in[0];
    const float* Wih_f = (const float*)d_in[1];
    const float* Whh_f = (const float*)d_in[2];
    const float* bih_f = (const float*)d_in[3];
    const float* bhh_f = (const float*)d_in[4];
    const float* Wih_b = (const float*)d_in[5];
    const float* Whh_b = (const float*)d_in[6];
    const float* bih_b = (const float*)d_in[7];
    const float* bhh_b = (const float*)d_in[8];
    const float* W1    = (const float*)d_in[9];
    const float* b1    = (const float*)d_in[10];
    const float* W2    = (const float*)d_in[11];
    const float* b2    = (const float*)d_in[12];
    float* out = (float*)d_out;

    xproj_kernel<<<2 * Bx * (Tx / XTK), 256>>>(x, Wih_f, bih_f, bhh_f, Wih_b, bih_b, bhh_b);
    lstm_kernel<<<2 * 128, 128>>>(Whh_f, Whh_b);   // 2 seqs/block, 2 blocks/SM
    head_kernel<<<(Bx * Tx) / 128, 256>>>(W1, b1, W2, b2, out);
}

// round 8
// speedup vs baseline: 1.2841x; 1.2841x over previous
#include <cuda_runtime.h>
#include <cstdint>

// Problem constants
#define Bx 256
#define Tx 3000
#define Ix 40
#define Hx 64
#define Gx 256        // 4*H gates
#define RCH 8         // recurrent x_proj chunk steps (3000 % 8 == 0 -> 375 chunks)
#define XTK 50        // xproj tokens per block tile (3000 % 50 == 0)

// Scratch (allocation-free rule: __device__ globals)
__device__ float g_h[2][(size_t)Bx * Tx * Hx];    // per-direction hidden outputs
__device__ float g_xp[2][(size_t)Bx * Tx * Gx];   // input projections (+biases); dir1 time-reversed

// ---------- packed f32x2 helpers ----------
union F2U { float2 f; unsigned long long u; };

__device__ __forceinline__ void ffma2(unsigned long long& acc,
                                      unsigned long long a,
                                      unsigned long long b) {
    asm("fma.rn.f32x2 %0, %1, %2, %0;" : "+l"(acc) : "l"(a), "l"(b));
}
__device__ __forceinline__ unsigned long long fadd2(unsigned long long a, unsigned long long b) {
    unsigned long long r;
    asm("add.rn.f32x2 %0, %1, %2;" : "=l"(r) : "l"(a), "l"(b));
    return r;
}
__device__ __forceinline__ float fsigmoid(float x) {
    return __fdividef(1.0f, 1.0f + __expf(-x));
}
__device__ __forceinline__ float ftanh_fast(float x) {
    return 1.0f - __fdividef(2.0f, __expf(2.0f * x) + 1.0f);
}
__device__ __forceinline__ float hsum2(unsigned long long a, unsigned long long b) {
    F2U s; s.u = fadd2(a, b);
    return s.f.x + s.f.y;
}

// ---------- cp.async helpers ----------
__device__ __forceinline__ unsigned int smem_u32(const void* p) {
    return (unsigned int)__cvta_generic_to_shared(p);
}
__device__ __forceinline__ void cp_async16(unsigned int s, const void* g) {
    asm volatile("cp.async.cg.shared.global [%0], [%1], 16;" :: "r"(s), "l"(g));
}
#define CP_COMMIT() asm volatile("cp.async.commit_group;")
#define CP_WAIT1()  asm volatile("cp.async.wait_group 1;")

// ================= x-projection kernel =================
// ONE direction per block (low regs -> 4 blocks/SM). Thread g = gate g.
// 2-token unroll; dir1 output stored time-reversed.
__global__ __launch_bounds__(256, 4)
void xproj_kernel(const float* __restrict__ x,
                  const float* __restrict__ WihF, const float* __restrict__ bihF,
                  const float* __restrict__ bhhF,
                  const float* __restrict__ WihB, const float* __restrict__ bihB,
                  const float* __restrict__ bhhB)
{
    const int g = threadIdx.x;
    __shared__ __align__(16) float sx[XTK * Ix];   // 8 KB

    const int dir  = blockIdx.x & 1;
    const int rest = blockIdx.x >> 1;
    const int tiles = Tx / XTK;                    // 60
    const int batch = rest / tiles;
    const int trel  = (rest % tiles) * XTK;

    const float* Wih = dir ? WihB : WihF;
    unsigned long long w[20];
    {
        const float2* wr = (const float2*)(Wih + (size_t)g * Ix);
        #pragma unroll
        for (int j = 0; j < 20; j++) { F2U u; u.f = wr[j]; w[j] = u.u; }
    }
    const float bias = dir ? (bihB[g] + bhhB[g]) : (bihF[g] + bhhF[g]);

    {
        const float4* xs = (const float4*)(x + ((size_t)batch * Tx + trel) * Ix);
        float4* sd = (float4*)sx;
        #pragma unroll
        for (int i = 0; i < 2; i++) {
            int idx = threadIdx.x + i * 256;
            if (idx < XTK * Ix / 4) sd[idx] = xs[idx];
        }
    }
    __syncthreads();

    const int t0 = dir ? (Tx - 1 - trel) : trel;
    const ptrdiff_t pstep = dir ? -(ptrdiff_t)Gx : (ptrdiff_t)Gx;
    float* p = g_xp[dir] + ((size_t)batch * Tx + t0) * Gx + g;
    const ulonglong2* xr = (const ulonglong2*)sx;

    #pragma unroll 1
    for (int k = 0; k < XTK / 2; k++) {
        F2U a0, a1, b0, b1;
        a0.f = make_float2(bias, 0.0f); a1.f = make_float2(0.0f, 0.0f);
        b0 = a0; b1 = a1;
        #pragma unroll
        for (int j = 0; j < 10; j++) {
            const ulonglong2 ua = xr[j];        // token 2k
            const ulonglong2 ub = xr[10 + j];   // token 2k+1
            ffma2(a0.u, ua.x, w[2 * j]);  ffma2(a1.u, ua.y, w[2 * j + 1]);
            ffma2(b0.u, ub.x, w[2 * j]);  ffma2(b1.u, ub.y, w[2 * j + 1]);
        }
        xr += 20;
        p[0]          = hsum2(a0.u, a1.u);
        *(p + pstep)  = hsum2(b0.u, b1.u);
        p += 2 * pstep;
    }
}

// ================= recurrent LSTM kernel =================
// Warp-local gate layout: lane l of warp w -> gate type r=l>>3, index
// u = w*8 + (l&7). All 4 gates of index u live in ONE warp, so the gate
// exchange is 3 shfl_down (no sgates SMEM), and with double-buffered sh
// each timestep needs ONE __syncthreads.
// 256 blocks x 256 threads, 2 seqs/block, one W_hh row per thread (64 regs),
// 2 blocks/SM (co-resident barrier domains overlap stalls).
__global__ __launch_bounds__(256, 2)
void lstm_kernel(const float* __restrict__ Whh_f, const float* __restrict__ Whh_b)
{
    const int dir   = blockIdx.x >> 7;          // 0..127 fwd, 128..255 bwd
    const int bbase = (blockIdx.x & 127) * 2;   // batches bbase, bbase+1

    const float* Whh = dir ? Whh_b : Whh_f;
    float* hout = g_h[dir];
    const float* xpd = g_xp[dir];

    const int tid = threadIdx.x;
    const int w   = tid >> 5;                   // warp 0..7
    const int l   = tid & 31;
    const int r   = l >> 3;                     // gate type: 0 i, 1 f, 2 g, 3 o
    const int u   = w * 8 + (l & 7);            // h index 0..63
    const int row = r * 64 + u;                 // W_hh row / x_proj column

    // branchless activation constants: tanh(v) = 2*sigmoid(2v) - 1
    const float km = (r == 2) ? 2.0f : 1.0f;
    const float ab = (r == 2) ? -1.0f : 0.0f;

    __shared__ __align__(16) float sxp[2][2][RCH * Gx];  // [seq][buf] 32 KB
    __shared__ __align__(16) float sh[2][2][Hx];         // [parity][seq] 1 KB

    // one W_hh row (64 floats = 32 f32x2) in registers
    unsigned long long whh[32];
    {
        const float2* wr = (const float2*)(Whh + (size_t)row * Hx);
        #pragma unroll
        for (int j = 0; j < 32; j++) { F2U a; a.f = wr[j]; whh[j] = a.u; }
    }

    if (r == 0) { sh[0][0][u] = 0.0f; sh[0][1][u] = 0.0f; }
    float cA = 0.0f, cB = 0.0f;       // meaningful in lanes r==0 only

    // cp.async slice: 128 threads per seq, 64B each (chunk = 8KB/seq)
    const int cseq = tid >> 7;
    const char* xsrc = (const char*)(xpd + (size_t)(bbase + cseq) * Tx * Gx) + (tid & 127) * 64;
    const unsigned int sdst0 = smem_u32(&sxp[cseq][0][0]) + (tid & 127) * 64;
    const unsigned int sdst1 = smem_u32(&sxp[cseq][1][0]) + (tid & 127) * 64;
    const int CHBYTES = RCH * Gx * 4;   // 8192

    // h output pointers (valid lanes r==0)
    float* hA = hout + ((size_t)(bbase + 0) * Tx + (dir ? (Tx - 1) : 0)) * Hx + u;
    float* hB = hout + ((size_t)(bbase + 1) * Tx + (dir ? (Tx - 1) : 0)) * Hx + u;
    const ptrdiff_t hstep = dir ? -Hx : Hx;

    // prefetch chunk 0 into buffer 0
    #pragma unroll
    for (int i = 0; i < 4; i++) cp_async16(sdst0 + i * 16, xsrc + i * 16);
    CP_COMMIT();

    int par = 0;
    const int NCH = Tx / RCH;
    for (int ck = 0; ck < NCH; ck++) {
        // prefetch ck+1; commit; wait for ck; barrier (R3-proven pattern)
        if (ck + 1 < NCH) {
            const unsigned int sdst = ((ck + 1) & 1) ? sdst1 : sdst0;
            const char* gsrc = xsrc + (size_t)(ck + 1) * CHBYTES;
            #pragma unroll
            for (int i = 0; i < 4; i++) cp_async16(sdst + i * 16, gsrc + i * 16);
        }
        CP_COMMIT();
        CP_WAIT1();
        __syncthreads();

        const float* xbA = sxp[0][ck & 1];
        const float* xbB = sxp[1][ck & 1];

        #pragma unroll 1
        for (int si = 0; si < RCH; si++) {
            // gate pre-activations for both sequences
            const float xvA = xbA[si * Gx + row];
            const float xvB = xbB[si * Gx + row];

            F2U a0A, a1A, a0B, a1B;
            a0A.f = make_float2(xvA, 0.0f); a1A.f = make_float2(0.0f, 0.0f);
            a0B.f = make_float2(xvB, 0.0f); a1B.f = a1A.f;

            const ulonglong2* hvA = (const ulonglong2*)sh[par][0];  // broadcast
            const ulonglong2* hvB = (const ulonglong2*)sh[par][1];
            #pragma unroll
            for (int k = 0; k < 16; k++) {
                const ulonglong2 ua = hvA[k];
                const ulonglong2 ub = hvB[k];
                ffma2(a0A.u, ua.x, whh[2 * k]);
                ffma2(a1A.u, ua.y, whh[2 * k + 1]);
                ffma2(a0B.u, ub.x, whh[2 * k]);
                ffma2(a1B.u, ub.y, whh[2 * k + 1]);
            }
            const float vA = hsum2(a0A.u, a1A.u);
            const float vB = hsum2(a0B.u, a1B.u);

            // branchless activation: sigmoid for r!=2, tanh via 2s(2v)-1 for r==2
            const float aA = fmaf(fsigmoid(vA * km), km, ab);
            const float aB = fmaf(fsigmoid(vB * km), km, ab);

            // warp-local gate gather into lanes r==0
            const float fA = __shfl_down_sync(0xffffffffu, aA, 8);
            const float gA = __shfl_down_sync(0xffffffffu, aA, 16);
            const float oA = __shfl_down_sync(0xffffffffu, aA, 24);
            const float fB = __shfl_down_sync(0xffffffffu, aB, 8);
            const float gB = __shfl_down_sync(0xffffffffu, aB, 16);
            const float oB = __shfl_down_sync(0xffffffffu, aB, 24);

            // c/h update (valid in lanes r==0; garbage elsewhere, unused)
            cA = fA * cA + aA * gA;
            cB = fB * cB + aB * gB;
            const float nhA = oA * ftanh_fast(cA);
            const float nhB = oB * ftanh_fast(cB);

            if (r == 0) {
                sh[par ^ 1][0][u] = nhA;
                sh[par ^ 1][1][u] = nhB;
                *hA = nhA;
                *hB = nhB;
            }
            hA += hstep;
            hB += hstep;
            par ^= 1;
            __syncthreads();   // single barrier per timestep
        }
    }
}

// ================= MLP head kernel =================
// 2 lanes per token (hf/hb halves), shfl-combine per output unit.
__global__ __launch_bounds__(256, 2)
void head_kernel(const float* __restrict__ W1, const float* __restrict__ b1,
                 const float* __restrict__ W2, const float* __restrict__ b2,
                 float* __restrict__ out)
{
    __shared__ __align__(16) float sW1[64 * 128];  // 32 KB
    __shared__ float sb1[64];
    __shared__ float sW2[64];

    const int tid = threadIdx.x;
    for (int i = tid; i < 64 * 128 / 4; i += 256)
        ((float4*)sW1)[i] = ((const float4*)W1)[i];
    if (tid < 64) { sb1[tid] = b1[tid]; sW2[tid] = W2[tid]; }
    __syncthreads();
    const float bias2 = b2[0];

    const size_t tok = (size_t)blockIdx.x * 128 + (tid >> 1);
    const int hsel = tid & 1;

    unsigned long long hreg[32];
    {
        const ulonglong2* hv = (const ulonglong2*)(g_h[hsel] + tok * Hx);
        #pragma unroll
        for (int j = 0; j < 16; j++) {
            ulonglong2 u = hv[j];
            hreg[2 * j] = u.x; hreg[2 * j + 1] = u.y;
        }
    }

    float acc = bias2;
    #pragma unroll 4
    for (int o = 0; o < 64; o++) {
        const unsigned long long* w =
            (const unsigned long long*)(sW1 + o * 128 + hsel * 64);
        F2U a0, a1, a2, a3;
        a0.f = make_float2(0.0f, 0.0f);
        a1 = a0; a2 = a0; a3 = a0;
        #pragma unroll
        for (int j = 0; j < 8; j++) {
            ffma2(a0.u, hreg[j],      w[j]);
            ffma2(a1.u, hreg[8 + j],  w[8 + j]);
            ffma2(a2.u, hreg[16 + j], w[16 + j]);
            ffma2(a3.u, hreg[24 + j], w[24 + j]);
        }
        F2U sx; sx.u = fadd2(fadd2(a0.u, a1.u), fadd2(a2.u, a3.u));
        float v = sx.f.x + sx.f.y;
        v += __shfl_xor_sync(0xffffffffu, v, 1);
        const float z = fmaxf(v + sb1[o], 0.0f);
        acc = fmaf(z, sW2[o], acc);
    }
    if (hsel == 0) out[tok] = fsigmoid(acc);
}

// ================= launch =================
extern "C" void kernel_launch(void* const* d_in, const int* in_sizes, int n_in,
                              void* d_out, int out_size)
{
    const float* x     = (const float*)d_in[0];
    const float* Wih_f = (const float*)d_in[1];
    const float* Whh_f = (const float*)d_in[2];
    const float* bih_f = (const float*)d_in[3];
    const float* bhh_f = (const float*)d_in[4];
    const float* Wih_b = (const float*)d_in[5];
    const float* Whh_b = (const float*)d_in[6];
    const float* bih_b = (const float*)d_in[7];
    const float* bhh_b = (const float*)d_in[8];
    const float* W1    = (const float*)d_in[9];
    const float* b1    = (const float*)d_in[10];
    const float* W2    = (const float*)d_in[11];
    const float* b2    = (const float*)d_in[12];
    float* out = (float*)d_out;

    xproj_kernel<<<2 * Bx * (Tx / XTK), 256>>>(x, Wih_f, bih_f, bhh_f, Wih_b, bih_b, bhh_b);
    lstm_kernel<<<2 * 128, 256>>>(Whh_f, Whh_b);   // 2 seqs/block, 2 blocks/SM
    head_kernel<<<(Bx * Tx) / 128, 256>>>(W1, b1, W2, b2, out);
}